// round 4
// baseline (speedup 1.0000x reference)
#include <cuda_runtime.h>

// ContrastivePredictionLoss — fused single-kernel, R3:
//  - plain LDG in the streaming loop (revert __ldcs; R1's loop hit 6.2 TB/s)
//  - __launch_bounds__(256, 8): force <=32 regs -> 8 blocks/SM, 100% occupancy
//    (R2 fused version had 38 regs -> 6 blocks/SM -> 61% DRAM, 5.0 TB/s)
//  - threadfence only on the one thread that wrote partials

#define NB 64
#define ELEMS_PER_BATCH (4 * 256 * 256)      // 262144
#define BLOCKS_PER_BATCH 32
#define NBLOCKS (NB * BLOCKS_PER_BATCH)      // 2048
#define THREADS_A 256
#define ELEMS_PER_BLOCK (ELEMS_PER_BATCH / BLOCKS_PER_BATCH)   // 8192
#define VECS_PER_BLOCK (ELEMS_PER_BLOCK / 4)                   // 2048 float4
#define VECS_PER_THREAD (VECS_PER_BLOCK / THREADS_A)           // 8

// Scratch (allocation-free __device__ globals).
__device__ float g_part_err[NBLOCKS];
__device__ float g_part_unc[NBLOCKS];
__device__ unsigned int g_ticket = 0;   // reset to 0 by the last block each call

__global__ __launch_bounds__(THREADS_A, 8)
void cpl_fused_kernel(const float4* __restrict__ pm,
                      const float4* __restrict__ ps,
                      const float4* __restrict__ tg,
                      float* __restrict__ out) {
    const int blk = blockIdx.x;                      // b * 32 + chunk
    const int tid = threadIdx.x;
    const long base = (long)blk * VECS_PER_BLOCK;

    float se = 0.0f;   // sum |pm - tg|
    float su = 0.0f;   // sum ps

    #pragma unroll
    for (int i = 0; i < VECS_PER_THREAD; i++) {
        const long idx = base + (long)i * THREADS_A + tid;
        float4 m = pm[idx];
        float4 t = tg[idx];
        float4 s = ps[idx];
        se += fabsf(m.x - t.x) + fabsf(m.y - t.y)
            + fabsf(m.z - t.z) + fabsf(m.w - t.w);
        su += s.x + s.y + s.z + s.w;
    }

    // Warp reduce (deterministic shuffle tree)
    #pragma unroll
    for (int off = 16; off > 0; off >>= 1) {
        se += __shfl_down_sync(0xFFFFFFFFu, se, off);
        su += __shfl_down_sync(0xFFFFFFFFu, su, off);
    }

    __shared__ float s_se[THREADS_A / 32];
    __shared__ float s_su[THREADS_A / 32];
    const int wid = tid >> 5;
    const int lid = tid & 31;
    if (lid == 0) { s_se[wid] = se; s_su[wid] = su; }
    __syncthreads();

    if (wid == 0) {
        se = (lid < THREADS_A / 32) ? s_se[lid] : 0.0f;
        su = (lid < THREADS_A / 32) ? s_su[lid] : 0.0f;
        #pragma unroll
        for (int off = 4; off > 0; off >>= 1) {
            se += __shfl_down_sync(0xFFFFFFFFu, se, off);
            su += __shfl_down_sync(0xFFFFFFFFu, su, off);
        }
        if (lid == 0) {
            g_part_err[blk] = se;
            g_part_unc[blk] = su;
        }
    }

    // ---- last-block-finalizes handshake ----
    __shared__ bool is_last;
    if (tid == 0) {
        __threadfence();                       // publish this block's partials
        unsigned int t = atomicAdd(&g_ticket, 1u);
        is_last = (t == NBLOCKS - 1);
        if (is_last) g_ticket = 0;             // reset for next graph replay
    }
    __syncthreads();
    if (!is_last) return;
    __threadfence();                           // acquire all partials

    // ---- finalize (one block, 256 threads) ----
    __shared__ float errs[NB];
    __shared__ float uncs[NB];

    if (tid < NB) {
        float pe = 0.0f, pu = 0.0f;
        #pragma unroll 4
        for (int c = 0; c < BLOCKS_PER_BATCH; c++) {
            // L2-scope loads: partials were written by other SMs; bypass L1.
            pe += __ldcg(&g_part_err[tid * BLOCKS_PER_BATCH + c]);
            pu += __ldcg(&g_part_unc[tid * BLOCKS_PER_BATCH + c]);
        }
        const float inv = 1.0f / (float)ELEMS_PER_BATCH;
        errs[tid] = pe * inv;
        uncs[tid] = pu * inv;
    }
    __syncthreads();

    // Pairwise hinge over upper triangle (i < j), fixed iteration order.
    float acc = 0.0f;
    for (int p = tid; p < NB * NB; p += THREADS_A) {
        const int i = p >> 6;
        const int j = p & 63;
        if (i < j) {
            const float d = ((errs[i] > errs[j]) ? (uncs[j] - uncs[i])
                                                 : (uncs[i] - uncs[j])) + 1.0f;
            acc += fmaxf(d, 0.0f);
        }
    }

    #pragma unroll
    for (int off = 16; off > 0; off >>= 1)
        acc += __shfl_down_sync(0xFFFFFFFFu, acc, off);

    __shared__ float s_acc[THREADS_A / 32];
    if (lid == 0) s_acc[wid] = acc;
    __syncthreads();

    if (tid == 0) {
        float total = 0.0f;
        #pragma unroll
        for (int w = 0; w < THREADS_A / 32; w++) total += s_acc[w];
        const int num_pairs = NB * (NB - 1) / 2;   // 2016
        out[0] = total / (float)num_pairs;
    }
}

extern "C" void kernel_launch(void* const* d_in, const int* in_sizes, int n_in,
                              void* d_out, int out_size) {
    const float4* pm = (const float4*)d_in[0];   // pred_mean
    const float4* ps = (const float4*)d_in[1];   // pred_std
    const float4* tg = (const float4*)d_in[2];   // targets
    float* out = (float*)d_out;

    cpl_fused_kernel<<<NBLOCKS, THREADS_A>>>(pm, ps, tg, out);
}